// round 1
// baseline (speedup 1.0000x reference)
#include <cuda_runtime.h>
#include <cuda_bf16.h>
#include <cstdint>

// Problem constants (fixed by the dataset)
#define N_NODES  100000
#define N_GRAPHS 2048
#define HID      64
#define N_CL     2

// ---------------- scratch (static device globals; no allocs allowed) --------
__device__ float g_dinv[N_NODES];              // deg -> dinv in place
__device__ float g_t[(size_t)N_NODES * HID];   // h @ W   (messages source)
__device__ float g_h[(size_t)N_NODES * HID];   // scatter destination / layer output
__device__ float g_sums[(size_t)N_GRAPHS * HID];
__device__ float g_cnts[N_GRAPHS];

// ---------------- helpers ---------------------------------------------------
__device__ __forceinline__ void red_add_v4(float* addr, float4 v) {
    asm volatile("red.global.add.v4.f32 [%0], {%1,%2,%3,%4};"
                 :: "l"(addr), "f"(v.x), "f"(v.y), "f"(v.z), "f"(v.w)
                 : "memory");
}

// ---------------- kernels ---------------------------------------------------

// deg init: self-loop contributes 1 to every node
__global__ void k_init_deg(int n) {
    int i = blockIdx.x * blockDim.x + threadIdx.x;
    if (i < n) g_dinv[i] = 1.0f;
}

__global__ void k_deg_edges(const int* __restrict__ col, int E) {
    int e = blockIdx.x * blockDim.x + threadIdx.x;
    if (e < E) atomicAdd(&g_dinv[col[e]], 1.0f);
}

__global__ void k_rsqrt(int n) {
    int i = blockIdx.x * blockDim.x + threadIdx.x;
    if (i < n) g_dinv[i] = rsqrtf(g_dinv[i]);   // deg >= 1 always (self loops)
}

// t[node] = emb[x[node]] @ W   (warp per node, W in smem, shuffle-broadcast e)
__global__ void k_mm_embed(const int* __restrict__ x,
                           const float* __restrict__ emb,
                           const float* __restrict__ W, int n) {
    __shared__ float sW[HID * HID];
    int tid = threadIdx.x;
    for (int i = tid; i < HID * HID; i += blockDim.x) sW[i] = W[i];
    __syncthreads();
    int lane = tid & 31;
    int warp = tid >> 5;
    int wpb  = blockDim.x >> 5;
    for (int node = blockIdx.x * wpb + warp; node < n; node += gridDim.x * wpb) {
        const float* e = emb + (size_t)x[node] * HID;
        float e_lo = e[lane];
        float e_hi = e[lane + 32];
        float a0 = 0.f, a1 = 0.f;
        #pragma unroll
        for (int k = 0; k < 32; k++) {
            float ek = __shfl_sync(0xffffffffu, e_lo, k);
            a0 = fmaf(ek, sW[k * HID + lane],      a0);
            a1 = fmaf(ek, sW[k * HID + 32 + lane], a1);
        }
        #pragma unroll
        for (int k = 0; k < 32; k++) {
            float ek = __shfl_sync(0xffffffffu, e_hi, k);
            a0 = fmaf(ek, sW[(k + 32) * HID + lane],      a0);
            a1 = fmaf(ek, sW[(k + 32) * HID + 32 + lane], a1);
        }
        float* t = g_t + (size_t)node * HID;
        t[lane]      = a0;
        t[lane + 32] = a1;
    }
}

// t[node] = relu(g_h[node]) @ W
__global__ void k_mm_hidden(const float* __restrict__ W, int n) {
    __shared__ float sW[HID * HID];
    int tid = threadIdx.x;
    for (int i = tid; i < HID * HID; i += blockDim.x) sW[i] = W[i];
    __syncthreads();
    int lane = tid & 31;
    int warp = tid >> 5;
    int wpb  = blockDim.x >> 5;
    for (int node = blockIdx.x * wpb + warp; node < n; node += gridDim.x * wpb) {
        const float* h = g_h + (size_t)node * HID;
        float e_lo = fmaxf(h[lane], 0.f);
        float e_hi = fmaxf(h[lane + 32], 0.f);
        float a0 = 0.f, a1 = 0.f;
        #pragma unroll
        for (int k = 0; k < 32; k++) {
            float ek = __shfl_sync(0xffffffffu, e_lo, k);
            a0 = fmaf(ek, sW[k * HID + lane],      a0);
            a1 = fmaf(ek, sW[k * HID + 32 + lane], a1);
        }
        #pragma unroll
        for (int k = 0; k < 32; k++) {
            float ek = __shfl_sync(0xffffffffu, e_hi, k);
            a0 = fmaf(ek, sW[(k + 32) * HID + lane],      a0);
            a1 = fmaf(ek, sW[(k + 32) * HID + 32 + lane], a1);
        }
        float* t = g_t + (size_t)node * HID;
        t[lane]      = a0;
        t[lane + 32] = a1;
    }
}

// h[i] = b + t[i] * dinv[i]^2   (bias + self-loop message fused)
__global__ void k_scatter_init(const float* __restrict__ b, int n) {
    int gid = blockIdx.x * blockDim.x + threadIdx.x;
    int i = gid >> 4;
    if (i >= n) return;
    int lane = gid & 15;
    float d = g_dinv[i];
    float d2 = d * d;
    float4 bv = reinterpret_cast<const float4*>(b)[lane];
    float4 tv = reinterpret_cast<const float4*>(g_t + (size_t)i * HID)[lane];
    float4 o;
    o.x = bv.x + tv.x * d2;
    o.y = bv.y + tv.y * d2;
    o.z = bv.z + tv.z * d2;
    o.w = bv.w + tv.w * d2;
    reinterpret_cast<float4*>(g_h + (size_t)i * HID)[lane] = o;
}

// h[col] += t[row] * dinv[row]*dinv[col]   (16 lanes x float4 per edge)
__global__ void k_edge_scatter(const int* __restrict__ row,
                               const int* __restrict__ col, int E) {
    int gid = blockIdx.x * blockDim.x + threadIdx.x;
    int e = gid >> 4;
    if (e >= E) return;
    int lane = gid & 15;
    int r = row[e];
    int c = col[e];
    float w = g_dinv[r] * g_dinv[c];
    float4 v = reinterpret_cast<const float4*>(g_t + (size_t)r * HID)[lane];
    v.x *= w; v.y *= w; v.z *= w; v.w *= w;
    red_add_v4(g_h + (size_t)c * HID + lane * 4, v);
}

__global__ void k_zero_pool() {
    int i = blockIdx.x * blockDim.x + threadIdx.x;
    if (i < N_GRAPHS * HID) g_sums[i] = 0.f;
    if (i < N_GRAPHS) g_cnts[i] = 0.f;
}

// sums[batch[i]] += relu(h[i]); cnts[batch[i]] += 1
__global__ void k_pool(const int* __restrict__ batch, int n) {
    int gid = blockIdx.x * blockDim.x + threadIdx.x;
    int i = gid >> 4;
    if (i >= n) return;
    int lane = gid & 15;
    int g = batch[i];
    float4 v = reinterpret_cast<const float4*>(g_h + (size_t)i * HID)[lane];
    v.x = fmaxf(v.x, 0.f); v.y = fmaxf(v.y, 0.f);
    v.z = fmaxf(v.z, 0.f); v.w = fmaxf(v.w, 0.f);
    red_add_v4(g_sums + (size_t)g * HID + lane * 4, v);
    if (lane == 0) atomicAdd(&g_cnts[g], 1.0f);
}

// out[g] = (sums[g]/max(cnt,1)) @ Wl + bl   (warp per graph)
__global__ void k_final(const float* __restrict__ Wl,
                        const float* __restrict__ bl,
                        float* __restrict__ out) {
    int lane = threadIdx.x & 31;
    int warp = threadIdx.x >> 5;
    int wpb  = blockDim.x >> 5;
    int g = blockIdx.x * wpb + warp;
    if (g >= N_GRAPHS) return;
    float inv = 1.0f / fmaxf(g_cnts[g], 1.0f);
    float s0 = g_sums[(size_t)g * HID + lane] * inv;
    float s1 = g_sums[(size_t)g * HID + 32 + lane] * inv;
    float a0 = s0 * Wl[lane * N_CL + 0] + s1 * Wl[(lane + 32) * N_CL + 0];
    float a1 = s0 * Wl[lane * N_CL + 1] + s1 * Wl[(lane + 32) * N_CL + 1];
    #pragma unroll
    for (int off = 16; off > 0; off >>= 1) {
        a0 += __shfl_down_sync(0xffffffffu, a0, off);
        a1 += __shfl_down_sync(0xffffffffu, a1, off);
    }
    if (lane == 0) {
        out[g * N_CL + 0] = a0 + bl[0];
        out[g * N_CL + 1] = a1 + bl[1];
    }
}

// ---------------- launch ----------------------------------------------------
extern "C" void kernel_launch(void* const* d_in, const int* in_sizes, int n_in,
                              void* d_out, int out_size) {
    const int*   x     = (const int*)  d_in[0];
    const int*   eidx  = (const int*)  d_in[1];
    const int*   batch = (const int*)  d_in[2];
    const float* emb   = (const float*)d_in[3];
    const float* W1    = (const float*)d_in[4];
    const float* b1    = (const float*)d_in[5];
    const float* W2    = (const float*)d_in[6];
    const float* b2    = (const float*)d_in[7];
    const float* Wl    = (const float*)d_in[8];
    const float* bl    = (const float*)d_in[9];
    float* out = (float*)d_out;

    const int N = in_sizes[0];
    const int E = in_sizes[1] / 2;
    const int* row = eidx;       // edge_index[0] = sources
    const int* col = eidx + E;   // edge_index[1] = targets

    const int T = 256;

    // degree / norm
    k_init_deg <<<(N + T - 1) / T, T>>>(N);
    k_deg_edges<<<(E + T - 1) / T, T>>>(col, E);
    k_zero_pool<<<(N_GRAPHS * HID + T - 1) / T, T>>>();
    k_rsqrt    <<<(N + T - 1) / T, T>>>(N);

    // layer 1
    k_mm_embed<<<2048, 256>>>(x, emb, W1, N);
    k_scatter_init<<<((N * 16) + T - 1) / T, T>>>(b1, N);
    k_edge_scatter<<<((E * 16) + T - 1) / T, T>>>(row, col, E);

    // layer 2
    k_mm_hidden<<<2048, 256>>>(W2, N);
    k_scatter_init<<<((N * 16) + T - 1) / T, T>>>(b2, N);
    k_edge_scatter<<<((E * 16) + T - 1) / T, T>>>(row, col, E);

    // pool + head
    k_pool<<<((N * 16) + T - 1) / T, T>>>(batch, N);
    k_final<<<(N_GRAPHS + 7) / 8, 256>>>(Wl, bl, out);
}

// round 3
// speedup vs baseline: 1.6342x; 1.6342x over previous
#include <cuda_runtime.h>
#include <cuda_bf16.h>
#include <cstdint>

#define N_NODESC 100000
#define N_EDGESC 1600000
#define N_GRAPHS 2048
#define VOCABC   1000
#define HID      64
#define N_CL     2
#define SCAN_B   1024

// ---------------- scratch (static device globals; no allocs) ----------------
// NOTE: these are ONLY ever referenced from device code (never passed as
// kernel arguments) — host-side symbol shadows are not device pointers.
__device__ int   g_degi[N_NODESC];
__device__ int   g_incl[N_NODESC];     // inclusive scan of deg -> CSR row ends
__device__ int   g_cursor[N_NODESC];
__device__ int   g_part[256];
__device__ int   g_gcnt[N_GRAPHS];
__device__ int   g_gincl[N_GRAPHS];    // inclusive scan of per-graph node counts
__device__ float g_dinv[N_NODESC];
__device__ int   g_csr[N_EDGESC];      // source node per CSR slot (grouped by target)
__device__ float g_tv[VOCABC * HID];   // emb @ W1 (vocab table)
__device__ float g_ts[(size_t)N_NODESC * HID];  // pre-scaled messages dinv*t
__device__ float g_h [(size_t)N_NODESC * HID];  // layer output

// ---------------- init / degree ---------------------------------------------
__global__ void k_zero(int n) {
    int i = blockIdx.x * blockDim.x + threadIdx.x;
    if (i < n) g_degi[i] = 0;
    if (i < N_GRAPHS) g_gcnt[i] = 0;
}

// counts: degi over edge targets; gcnt over batch
__global__ void k_count(const int* __restrict__ col,
                        const int* __restrict__ batch, int E, int N) {
    int i = blockIdx.x * blockDim.x + threadIdx.x;
    if (i < E) atomicAdd(&g_degi[col[i]], 1);
    else if (i < E + N) atomicAdd(&g_gcnt[batch[i - E]], 1);
}

// ---------------- scan machinery (device-global in/out, no ptr args) --------
__device__ __forceinline__ void scan_block_body(const int* in, int n, int* out) {
    __shared__ int s[SCAN_B];
    int base = blockIdx.x * SCAN_B;
    int t = threadIdx.x;
    int v = (base + t < n) ? in[base + t] : 0;
    s[t] = v;
    __syncthreads();
    #pragma unroll
    for (int off = 1; off < SCAN_B; off <<= 1) {
        int u = (t >= off) ? s[t - off] : 0;
        __syncthreads();
        s[t] += u;
        __syncthreads();
    }
    if (base + t < n) out[base + t] = s[t];
    if (t == SCAN_B - 1) g_part[blockIdx.x] = s[t];
}

__global__ void k_scan_deg_block(int n)  { scan_block_body(g_degi, n, g_incl); }
__global__ void k_scan_gcnt_block(int n) { scan_block_body(g_gcnt, n, g_gincl); }

__global__ void k_scan_part(int nb) {
    __shared__ int s[SCAN_B];
    int t = threadIdx.x;
    int v = (t < nb) ? g_part[t] : 0;
    s[t] = v;
    __syncthreads();
    #pragma unroll
    for (int off = 1; off < SCAN_B; off <<= 1) {
        int u = (t >= off) ? s[t - off] : 0;
        __syncthreads();
        s[t] += u;
        __syncthreads();
    }
    if (t < nb) g_part[t] = s[t] - v;   // exclusive prefix of block sums
}

__global__ void k_scan_add_incl(int n) {
    int base = blockIdx.x * SCAN_B;
    int t = threadIdx.x;
    if (blockIdx.x > 0 && base + t < n) g_incl[base + t] += g_part[blockIdx.x];
}
__global__ void k_scan_add_gincl(int n) {
    int base = blockIdx.x * SCAN_B;
    int t = threadIdx.x;
    if (blockIdx.x > 0 && base + t < n) g_gincl[base + t] += g_part[blockIdx.x];
}

// ---------------- norm + cursor ---------------------------------------------
__global__ void k_norm_cursor(int n) {
    int i = blockIdx.x * blockDim.x + threadIdx.x;
    if (i >= n) return;
    g_dinv[i] = rsqrtf((float)(g_degi[i] + 1));   // +1 self loop
    g_cursor[i] = (i == 0) ? 0 : g_incl[i - 1];
}

__global__ void k_fill_csr(const int* __restrict__ row,
                           const int* __restrict__ col, int E) {
    int e = blockIdx.x * blockDim.x + threadIdx.x;
    if (e >= E) return;
    int slot = atomicAdd(&g_cursor[col[e]], 1);
    g_csr[slot] = row[e];
}

// ---------------- vocab GEMM: g_tv = emb @ W1 (warp per vocab row) -----------
__global__ void k_vocab_mm(const float* __restrict__ emb,
                           const float* __restrict__ W, int V) {
    __shared__ float sW[HID * HID];
    int tid = threadIdx.x;
    for (int i = tid; i < HID * HID; i += blockDim.x) sW[i] = W[i];
    __syncthreads();
    int lane = tid & 31, warp = tid >> 5, wpb = blockDim.x >> 5;
    int r = blockIdx.x * wpb + warp;
    if (r >= V) return;
    const float* e = emb + (size_t)r * HID;
    float e_lo = e[lane], e_hi = e[lane + 32];
    float a0 = 0.f, a1 = 0.f;
    #pragma unroll
    for (int k = 0; k < 32; k++) {
        float ek = __shfl_sync(0xffffffffu, e_lo, k);
        a0 = fmaf(ek, sW[k * HID + lane],      a0);
        a1 = fmaf(ek, sW[k * HID + 32 + lane], a1);
    }
    #pragma unroll
    for (int k = 0; k < 32; k++) {
        float ek = __shfl_sync(0xffffffffu, e_hi, k);
        a0 = fmaf(ek, sW[(k + 32) * HID + lane],      a0);
        a1 = fmaf(ek, sW[(k + 32) * HID + 32 + lane], a1);
    }
    g_tv[(size_t)r * HID + lane]      = a0;
    g_tv[(size_t)r * HID + 32 + lane] = a1;
}

// ---------------- layer-1 message build: ts[i] = dinv[i] * tv[x[i]] ----------
__global__ void k_l1_ts(const int* __restrict__ x, int n) {
    int gid = blockIdx.x * blockDim.x + threadIdx.x;
    int i = gid >> 4;
    if (i >= n) return;
    int lane = gid & 15;
    float d = g_dinv[i];
    float4 v = reinterpret_cast<const float4*>(g_tv + (size_t)x[i] * HID)[lane];
    v.x *= d; v.y *= d; v.z *= d; v.w *= d;
    reinterpret_cast<float4*>(g_ts + (size_t)i * HID)[lane] = v;
}

// ---------------- CSR gather: h[c] = b + dinv[c]*(ts[c] + sum ts[r]) ---------
__global__ void k_gather(const float* __restrict__ b, int n) {
    int lane = threadIdx.x & 31;
    int warp = threadIdx.x >> 5;
    int c = blockIdx.x * (blockDim.x >> 5) + warp;
    if (c >= n) return;
    int start = (c == 0) ? 0 : g_incl[c - 1];
    int end = g_incl[c];
    const float* __restrict__ ts = g_ts;
    float a0 = ts[(size_t)c * HID + lane];
    float a1 = ts[(size_t)c * HID + 32 + lane];
    float b0 = 0.f, b1 = 0.f, c0 = 0.f, c1 = 0.f, d0 = 0.f, d1 = 0.f;
    int e = start;
    for (; e + 4 <= end; e += 4) {
        int r0 = g_csr[e], r1 = g_csr[e + 1], r2 = g_csr[e + 2], r3 = g_csr[e + 3];
        float v0a = ts[(size_t)r0 * HID + lane], v0b = ts[(size_t)r0 * HID + 32 + lane];
        float v1a = ts[(size_t)r1 * HID + lane], v1b = ts[(size_t)r1 * HID + 32 + lane];
        float v2a = ts[(size_t)r2 * HID + lane], v2b = ts[(size_t)r2 * HID + 32 + lane];
        float v3a = ts[(size_t)r3 * HID + lane], v3b = ts[(size_t)r3 * HID + 32 + lane];
        a0 += v0a; a1 += v0b;
        b0 += v1a; b1 += v1b;
        c0 += v2a; c1 += v2b;
        d0 += v3a; d1 += v3b;
    }
    for (; e < end; e++) {
        int r = g_csr[e];
        a0 += ts[(size_t)r * HID + lane];
        a1 += ts[(size_t)r * HID + 32 + lane];
    }
    a0 += b0 + c0 + d0;
    a1 += b1 + c1 + d1;
    float d = g_dinv[c];
    g_h[(size_t)c * HID + lane]      = fmaf(d, a0, b[lane]);
    g_h[(size_t)c * HID + 32 + lane] = fmaf(d, a1, b[lane + 32]);
}

// ---------------- hidden GEMM: ts = dinv .* (relu(h) @ W) --------------------
__global__ void k_mm_hidden(const float* __restrict__ W, int n) {
    __shared__ float sW[HID * HID];
    int tid = threadIdx.x;
    for (int i = tid; i < HID * HID; i += blockDim.x) sW[i] = W[i];
    __syncthreads();
    int lane = tid & 31, warp = tid >> 5, wpb = blockDim.x >> 5;
    for (int node = blockIdx.x * wpb + warp; node < n; node += gridDim.x * wpb) {
        const float* h = g_h + (size_t)node * HID;
        float e_lo = fmaxf(h[lane], 0.f);
        float e_hi = fmaxf(h[lane + 32], 0.f);
        float a0 = 0.f, a1 = 0.f;
        #pragma unroll
        for (int k = 0; k < 32; k++) {
            float ek = __shfl_sync(0xffffffffu, e_lo, k);
            a0 = fmaf(ek, sW[k * HID + lane],      a0);
            a1 = fmaf(ek, sW[k * HID + 32 + lane], a1);
        }
        #pragma unroll
        for (int k = 0; k < 32; k++) {
            float ek = __shfl_sync(0xffffffffu, e_hi, k);
            a0 = fmaf(ek, sW[(k + 32) * HID + lane],      a0);
            a1 = fmaf(ek, sW[(k + 32) * HID + 32 + lane], a1);
        }
        float d = g_dinv[node];
        float* t = g_ts + (size_t)node * HID;
        t[lane]      = a0 * d;
        t[lane + 32] = a1 * d;
    }
}

// ---------------- pool + head (warp per graph, batch is sorted) --------------
__global__ void k_pool_head(const float* __restrict__ Wl,
                            const float* __restrict__ bl,
                            float* __restrict__ out) {
    int lane = threadIdx.x & 31;
    int warp = threadIdx.x >> 5;
    int g = blockIdx.x * (blockDim.x >> 5) + warp;
    if (g >= N_GRAPHS) return;
    int start = (g == 0) ? 0 : g_gincl[g - 1];
    int end = g_gincl[g];
    float s0 = 0.f, s1 = 0.f;
    for (int i = start; i < end; i++) {
        s0 += fmaxf(g_h[(size_t)i * HID + lane], 0.f);
        s1 += fmaxf(g_h[(size_t)i * HID + 32 + lane], 0.f);
    }
    float inv = 1.0f / fmaxf((float)(end - start), 1.0f);
    s0 *= inv; s1 *= inv;
    float a0 = s0 * Wl[lane * N_CL + 0] + s1 * Wl[(lane + 32) * N_CL + 0];
    float a1 = s0 * Wl[lane * N_CL + 1] + s1 * Wl[(lane + 32) * N_CL + 1];
    #pragma unroll
    for (int off = 16; off > 0; off >>= 1) {
        a0 += __shfl_down_sync(0xffffffffu, a0, off);
        a1 += __shfl_down_sync(0xffffffffu, a1, off);
    }
    if (lane == 0) {
        out[g * N_CL + 0] = a0 + bl[0];
        out[g * N_CL + 1] = a1 + bl[1];
    }
}

// ---------------- launch ----------------------------------------------------
extern "C" void kernel_launch(void* const* d_in, const int* in_sizes, int n_in,
                              void* d_out, int out_size) {
    const int*   x     = (const int*)  d_in[0];
    const int*   eidx  = (const int*)  d_in[1];
    const int*   batch = (const int*)  d_in[2];
    const float* emb   = (const float*)d_in[3];
    const float* W1    = (const float*)d_in[4];
    const float* b1    = (const float*)d_in[5];
    const float* W2    = (const float*)d_in[6];
    const float* b2    = (const float*)d_in[7];
    const float* Wl    = (const float*)d_in[8];
    const float* bl    = (const float*)d_in[9];
    float* out = (float*)d_out;

    const int N = in_sizes[0];
    const int E = in_sizes[1] / 2;
    const int V = in_sizes[3] / HID;
    const int* row = eidx;       // sources
    const int* col = eidx + E;   // targets

    const int T = 256;
    int nbN = (N + SCAN_B - 1) / SCAN_B;
    int nbG = (N_GRAPHS + SCAN_B - 1) / SCAN_B;

    // counts
    k_zero <<<(N + T - 1) / T, T>>>(N);
    k_count<<<(E + N + T - 1) / T, T>>>(col, batch, E, N);

    // CSR rowptr (inclusive scan of deg)
    k_scan_deg_block<<<nbN, SCAN_B>>>(N);
    k_scan_part     <<<1, SCAN_B>>>(nbN);
    k_scan_add_incl <<<nbN, SCAN_B>>>(N);

    // norm + cursor, then CSR fill
    k_norm_cursor<<<(N + T - 1) / T, T>>>(N);
    k_fill_csr   <<<(E + T - 1) / T, T>>>(row, col, E);

    // graph offsets (inclusive scan of gcnt)
    k_scan_gcnt_block<<<nbG, SCAN_B>>>(N_GRAPHS);
    k_scan_part      <<<1, SCAN_B>>>(nbG);
    k_scan_add_gincl <<<nbG, SCAN_B>>>(N_GRAPHS);

    // layer 1: vocab GEMM + message build + gather
    k_vocab_mm<<<(V + 7) / 8, 256>>>(emb, W1, V);
    k_l1_ts   <<<((N * 16) + T - 1) / T, T>>>(x, N);
    k_gather  <<<(N + 7) / 8, 256>>>(b1, N);

    // layer 2
    k_mm_hidden<<<2048, 256>>>(W2, N);
    k_gather   <<<(N + 7) / 8, 256>>>(b2, N);

    // pool + head
    k_pool_head<<<(N_GRAPHS + 7) / 8, 256>>>(Wl, bl, out);
}

// round 5
// speedup vs baseline: 1.8216x; 1.1147x over previous
#include <cuda_runtime.h>
#include <cuda_fp16.h>
#include <cuda_bf16.h>
#include <cstdint>

#define N_NODESC 100000
#define N_EDGESC 1600000
#define N_GRAPHS 2048
#define VOCABC   1000
#define HID      64
#define N_CL     2
#define SCAN_B   1024
#define NB_N     ((N_NODESC + SCAN_B - 1) / SCAN_B)   // 98
#define NB_G     ((N_GRAPHS + SCAN_B - 1) / SCAN_B)   // 2

// ---------------- scratch (device globals; referenced ONLY from device code) -
__device__ int    g_degi[N_NODESC];
__device__ int    g_incl[N_NODESC];      // inclusive scan of deg (CSR row ends)
__device__ int    g_cursor[N_NODESC];
__device__ int    g_gcnt[N_GRAPHS];
__device__ int    g_gincl[N_GRAPHS];
__device__ int    g_bsum[NB_N + NB_G];
__device__ int    g_arrive;
__device__ float  g_dinv[N_NODESC];
__device__ int    g_csr[N_EDGESC];       // source node per CSR slot
__device__ float  g_tv[VOCABC * HID];    // emb @ W1 (fp32 vocab table)
__device__ __half g_ts[(size_t)N_NODESC * HID];  // pre-scaled messages (fp16)
__device__ float  g_h [(size_t)N_NODESC * HID];  // layer output (fp32)

// ---------------- init + counts ---------------------------------------------
__global__ void k_zero(int n) {
    int i = blockIdx.x * blockDim.x + threadIdx.x;
    if (i < n) g_degi[i] = 0;
    if (i < N_GRAPHS) g_gcnt[i] = 0;
    if (i == 0) g_arrive = 0;
}

__global__ void k_count(const int* __restrict__ col,
                        const int* __restrict__ batch, int E, int N) {
    int i = blockIdx.x * blockDim.x + threadIdx.x;
    if (i < E) atomicAdd(&g_degi[col[i]], 1);
    else if (i < E + N) atomicAdd(&g_gcnt[batch[i - E]], 1);
}

// ---------------- one-launch dual scan (all blocks wave-1 resident) ----------
__device__ __forceinline__ int warp_incl_scan(int x, int lane) {
    #pragma unroll
    for (int o = 1; o < 32; o <<= 1) {
        int u = __shfl_up_sync(0xffffffffu, x, o);
        if (lane >= o) x += u;
    }
    return x;
}

__global__ void k_scan_all(int N) {
    __shared__ int wsum[32];
    __shared__ int spre;
    int t = threadIdx.x, lane = t & 31, w = t >> 5;
    bool isDeg = blockIdx.x < NB_N;
    int lo  = isDeg ? 0 : NB_N;
    int n   = isDeg ? N : N_GRAPHS;
    int idx = (blockIdx.x - lo) * SCAN_B + t;
    int v   = 0;
    if (idx < n) v = isDeg ? g_degi[idx] : g_gcnt[idx];

    int incl = warp_incl_scan(v, lane);
    if (lane == 31) wsum[w] = incl;
    __syncthreads();
    if (w == 0) wsum[lane] = warp_incl_scan(wsum[lane], lane);
    __syncthreads();
    int blockIncl = incl + (w > 0 ? wsum[w - 1] : 0);
    int blockTot = wsum[31];

    if (t == 0) {
        g_bsum[blockIdx.x] = blockTot;
        __threadfence();
        atomicAdd(&g_arrive, 1);
        while (atomicAdd(&g_arrive, 0) < (int)gridDim.x) { }
    }
    __syncthreads();

    // exclusive block prefix over this chain (warp 0)
    if (w == 0) {
        int pre = 0;
        for (int j = lo + lane; j < (int)blockIdx.x; j += 32) pre += g_bsum[j];
        #pragma unroll
        for (int o = 16; o > 0; o >>= 1) pre += __shfl_down_sync(0xffffffffu, pre, o);
        if (lane == 0) spre = pre;
    }
    __syncthreads();
    int fin = blockIncl + spre;

    if (idx < n) {
        if (isDeg) {
            g_incl[idx]   = fin;
            g_cursor[idx] = fin - v;
            g_dinv[idx]   = rsqrtf((float)(v + 1));   // +1 self loop
        } else {
            g_gincl[idx] = fin;
        }
    }
}

// ---------------- vocab GEMM: g_tv = emb @ W1 (warp per vocab row, fp32) -----
__global__ void k_vocab_mm(const float* __restrict__ emb,
                           const float* __restrict__ W, int V) {
    __shared__ float sW[HID * HID];
    int tid = threadIdx.x;
    for (int i = tid; i < HID * HID; i += blockDim.x) sW[i] = W[i];
    __syncthreads();
    int lane = tid & 31, warp = tid >> 5, wpb = blockDim.x >> 5;
    int r = blockIdx.x * wpb + warp;
    if (r >= V) return;
    const float* e = emb + (size_t)r * HID;
    float e_lo = e[lane], e_hi = e[lane + 32];
    float a0 = 0.f, a1 = 0.f;
    #pragma unroll
    for (int k = 0; k < 32; k++) {
        float ek = __shfl_sync(0xffffffffu, e_lo, k);
        a0 = fmaf(ek, sW[k * HID + lane],      a0);
        a1 = fmaf(ek, sW[k * HID + 32 + lane], a1);
    }
    #pragma unroll
    for (int k = 0; k < 32; k++) {
        float ek = __shfl_sync(0xffffffffu, e_hi, k);
        a0 = fmaf(ek, sW[(k + 32) * HID + lane],      a0);
        a1 = fmaf(ek, sW[(k + 32) * HID + 32 + lane], a1);
    }
    g_tv[(size_t)r * HID + lane]      = a0;
    g_tv[(size_t)r * HID + 32 + lane] = a1;
}

// ---------------- fused: CSR fill (per-edge) + layer-1 fp16 messages ---------
__global__ void k_fill_l1(const int* __restrict__ row,
                          const int* __restrict__ col,
                          const int* __restrict__ x, int E, int N) {
    int i = blockIdx.x * blockDim.x + threadIdx.x;
    if (i < E) {
        int slot = atomicAdd(&g_cursor[col[i]], 1);
        g_csr[slot] = row[i];
    } else {
        int gid = i - E;            // 16 lanes per node
        int node = gid >> 4;
        if (node >= N) return;
        int lane = gid & 15;
        float d = g_dinv[node];
        float4 v = reinterpret_cast<const float4*>(g_tv + (size_t)x[node] * HID)[lane];
        __half2 h0 = __floats2half2_rn(v.x * d, v.y * d);
        __half2 h1 = __floats2half2_rn(v.z * d, v.w * d);
        uint2 u;
        u.x = *reinterpret_cast<unsigned int*>(&h0);
        u.y = *reinterpret_cast<unsigned int*>(&h1);
        reinterpret_cast<uint2*>(g_ts)[(size_t)node * 16 + lane] = u;
    }
}

// ---------------- CSR gather (fp16 msgs): h[c]=b+dinv[c]*(ts[c]+sum ts[r]) ---
__global__ void k_gather(const float* __restrict__ b, int n) {
    int lane = threadIdx.x & 31;
    int warp = threadIdx.x >> 5;
    int c = blockIdx.x * (blockDim.x >> 5) + warp;
    if (c >= n) return;
    int start = (c == 0) ? 0 : g_incl[c - 1];
    int end = g_incl[c];
    const __half2* __restrict__ ts = reinterpret_cast<const __half2*>(g_ts);
    float2 a0 = __half22float2(ts[(size_t)c * 32 + lane]);
    float2 a1 = make_float2(0.f, 0.f);
    float2 a2 = make_float2(0.f, 0.f);
    float2 a3 = make_float2(0.f, 0.f);
    int e = start;
    for (; e + 4 <= end; e += 4) {
        int r0 = g_csr[e], r1 = g_csr[e + 1], r2 = g_csr[e + 2], r3 = g_csr[e + 3];
        float2 v0 = __half22float2(ts[(size_t)r0 * 32 + lane]);
        float2 v1 = __half22float2(ts[(size_t)r1 * 32 + lane]);
        float2 v2 = __half22float2(ts[(size_t)r2 * 32 + lane]);
        float2 v3 = __half22float2(ts[(size_t)r3 * 32 + lane]);
        a0.x += v0.x; a0.y += v0.y;
        a1.x += v1.x; a1.y += v1.y;
        a2.x += v2.x; a2.y += v2.y;
        a3.x += v3.x; a3.y += v3.y;
    }
    for (; e < end; e++) {
        int r = g_csr[e];
        float2 v = __half22float2(ts[(size_t)r * 32 + lane]);
        a0.x += v.x; a0.y += v.y;
    }
    a0.x += a1.x + a2.x + a3.x;
    a0.y += a1.y + a2.y + a3.y;
    float d = g_dinv[c];
    float2 bb = reinterpret_cast<const float2*>(b)[lane];
    float2 o;
    o.x = fmaf(d, a0.x, bb.x);
    o.y = fmaf(d, a0.y, bb.y);
    reinterpret_cast<float2*>(g_h)[(size_t)c * 32 + lane] = o;
}

// ---------------- hidden GEMM: ts = fp16( dinv .* (relu(h) @ W) ) ------------
__global__ void k_mm_hidden(const float* __restrict__ W, int n) {
    __shared__ float sW[HID * HID];
    int tid = threadIdx.x;
    for (int i = tid; i < HID * HID; i += blockDim.x) sW[i] = W[i];
    __syncthreads();
    const float2* sW2 = reinterpret_cast<const float2*>(sW);
    int lane = tid & 31, warp = tid >> 5, wpb = blockDim.x >> 5;
    for (int node = blockIdx.x * wpb + warp; node < n; node += gridDim.x * wpb) {
        float2 h = reinterpret_cast<const float2*>(g_h)[(size_t)node * 32 + lane];
        float ex = fmaxf(h.x, 0.f);
        float ey = fmaxf(h.y, 0.f);
        float a = 0.f, bc = 0.f;
        #pragma unroll
        for (int j = 0; j < 32; j++) {
            float e0 = __shfl_sync(0xffffffffu, ex, j);
            float e1 = __shfl_sync(0xffffffffu, ey, j);
            float2 w0 = sW2[(2 * j) * 32 + lane];
            float2 w1 = sW2[(2 * j + 1) * 32 + lane];
            a  = fmaf(e0, w0.x, a);
            bc = fmaf(e0, w0.y, bc);
            a  = fmaf(e1, w1.x, a);
            bc = fmaf(e1, w1.y, bc);
        }
        float d = g_dinv[node];
        reinterpret_cast<__half2*>(g_ts)[(size_t)node * 32 + lane] =
            __floats2half2_rn(a * d, bc * d);
    }
}

// ---------------- pool + head (warp per graph, batch sorted) -----------------
__global__ void k_pool_head(const float* __restrict__ Wl,
                            const float* __restrict__ bl,
                            float* __restrict__ out) {
    int lane = threadIdx.x & 31;
    int warp = threadIdx.x >> 5;
    int g = blockIdx.x * (blockDim.x >> 5) + warp;
    if (g >= N_GRAPHS) return;
    int start = (g == 0) ? 0 : g_gincl[g - 1];
    int end = g_gincl[g];
    float s0 = 0.f, s1 = 0.f;
    for (int i = start; i < end; i++) {
        float2 v0 = reinterpret_cast<const float2*>(g_h)[(size_t)i * 32 + lane];
        s0 += fmaxf(v0.x, 0.f);
        s1 += fmaxf(v0.y, 0.f);
    }
    float inv = 1.0f / fmaxf((float)(end - start), 1.0f);
    s0 *= inv; s1 *= inv;
    // lane owns columns 2*lane, 2*lane+1
    float a0 = s0 * Wl[(2 * lane) * N_CL + 0] + s1 * Wl[(2 * lane + 1) * N_CL + 0];
    float a1 = s0 * Wl[(2 * lane) * N_CL + 1] + s1 * Wl[(2 * lane + 1) * N_CL + 1];
    #pragma unroll
    for (int off = 16; off > 0; off >>= 1) {
        a0 += __shfl_down_sync(0xffffffffu, a0, off);
        a1 += __shfl_down_sync(0xffffffffu, a1, off);
    }
    if (lane == 0) {
        out[g * N_CL + 0] = a0 + bl[0];
        out[g * N_CL + 1] = a1 + bl[1];
    }
}

// ---------------- launch ----------------------------------------------------
extern "C" void kernel_launch(void* const* d_in, const int* in_sizes, int n_in,
                              void* d_out, int out_size) {
    const int*   x     = (const int*)  d_in[0];
    const int*   eidx  = (const int*)  d_in[1];
    const int*   batch = (const int*)  d_in[2];
    const float* emb   = (const float*)d_in[3];
    const float* W1    = (const float*)d_in[4];
    const float* b1    = (const float*)d_in[5];
    const float* W2    = (const float*)d_in[6];
    const float* b2    = (const float*)d_in[7];
    const float* Wl    = (const float*)d_in[8];
    const float* bl    = (const float*)d_in[9];
    float* out = (float*)d_out;

    const int N = in_sizes[0];
    const int E = in_sizes[1] / 2;
    const int V = in_sizes[3] / HID;
    const int* row = eidx;       // sources
    const int* col = eidx + E;   // targets

    const int T = 256;

    // independent: vocab GEMM
    k_vocab_mm<<<(V + 7) / 8, 256>>>(emb, W1, V);

    // counts -> dual scan (single launch) -> CSR fill + layer-1 messages
    k_zero    <<<(N + T - 1) / T, T>>>(N);
    k_count   <<<(E + N + T - 1) / T, T>>>(col, batch, E, N);
    k_scan_all<<<NB_N + NB_G, SCAN_B>>>(N);
    k_fill_l1 <<<(E + 16 * N + T - 1) / T, T>>>(row, col, x, E, N);

    // layer 1 aggregate
    k_gather<<<(N + 7) / 8, 256>>>(b1, N);

    // layer 2
    k_mm_hidden<<<2048, 256>>>(W2, N);
    k_gather   <<<(N + 7) / 8, 256>>>(b2, N);

    // pool + head
    k_pool_head<<<(N_GRAPHS + 7) / 8, 256>>>(Wl, bl, out);
}

// round 6
// speedup vs baseline: 2.0530x; 1.1270x over previous
#include <cuda_runtime.h>
#include <cuda_fp16.h>
#include <cuda_bf16.h>
#include <cstdint>

#define N_NODESC 100000
#define N_EDGESC 1600000
#define N_GRAPHS 2048
#define VOCABC   1000
#define HID      64
#define N_CL     2
#define SCAN_B   1024
#define NB_N     ((N_NODESC + SCAN_B - 1) / SCAN_B)   // 98
#define NB_G     ((N_GRAPHS + SCAN_B - 1) / SCAN_B)   // 2
#define VB       ((VOCABC + 7) / 8)                   // vocab blocks (8 rows/block)

// ---------------- scratch (device globals; referenced ONLY from device code) -
__device__ int    g_degi[N_NODESC];
__device__ int    g_incl[N_NODESC];      // inclusive scan of deg (CSR row ends)
__device__ int    g_cursor[N_NODESC];
__device__ int    g_gcnt[N_GRAPHS];
__device__ int    g_gincl[N_GRAPHS];
__device__ int    g_bsum[NB_N + NB_G];
__device__ int    g_arrive;
__device__ float  g_dinv[N_NODESC];
__device__ int    g_csr[N_EDGESC];       // source node per CSR slot
__device__ float  g_tv[VOCABC * HID];    // emb @ W1 (fp32 vocab table)
__device__ __half g_ts [(size_t)N_NODESC * HID];  // layer-1 messages (fp16)
__device__ __half g_ts2[(size_t)N_NODESC * HID];  // layer-2 messages (fp16)
__device__ float  g_sums[(size_t)N_GRAPHS * HID]; // pooled sums

// ---------------- fused: zero scratch + vocab GEMM (emb @ W1) ----------------
__global__ void k_vocab_zero(const float* __restrict__ emb,
                             const float* __restrict__ W, int N, int V) {
    __shared__ float sW[HID * HID];
    if (blockIdx.x < VB) {
        int tid = threadIdx.x;
        for (int i = tid; i < HID * HID; i += blockDim.x) sW[i] = W[i];
        __syncthreads();
        int lane = tid & 31, warp = tid >> 5;
        int r = blockIdx.x * 8 + warp;
        if (r >= V) return;
        const float* e = emb + (size_t)r * HID;
        float e_lo = e[lane], e_hi = e[lane + 32];
        float a0 = 0.f, a1 = 0.f;
        #pragma unroll
        for (int k = 0; k < 32; k++) {
            float ek = __shfl_sync(0xffffffffu, e_lo, k);
            a0 = fmaf(ek, sW[k * HID + lane],      a0);
            a1 = fmaf(ek, sW[k * HID + 32 + lane], a1);
        }
        #pragma unroll
        for (int k = 0; k < 32; k++) {
            float ek = __shfl_sync(0xffffffffu, e_hi, k);
            a0 = fmaf(ek, sW[(k + 32) * HID + lane],      a0);
            a1 = fmaf(ek, sW[(k + 32) * HID + 32 + lane], a1);
        }
        g_tv[(size_t)r * HID + lane]      = a0;
        g_tv[(size_t)r * HID + 32 + lane] = a1;
    } else {
        int i = (blockIdx.x - VB) * blockDim.x + threadIdx.x;
        if (i < N) g_degi[i] = 0;
        if (i < N_GRAPHS) g_gcnt[i] = 0;
        if (i < N_GRAPHS * HID) g_sums[i] = 0.f;
        if (i == 0) g_arrive = 0;
    }
}

// ---------------- counts -----------------------------------------------------
__global__ void k_count(const int* __restrict__ col,
                        const int* __restrict__ batch, int E, int N) {
    int i = blockIdx.x * blockDim.x + threadIdx.x;
    if (i < E) atomicAdd(&g_degi[col[i]], 1);
    else if (i < E + N) atomicAdd(&g_gcnt[batch[i - E]], 1);
}

// ---------------- one-launch dual scan (all blocks wave-1 resident) ----------
__device__ __forceinline__ int warp_incl_scan(int x, int lane) {
    #pragma unroll
    for (int o = 1; o < 32; o <<= 1) {
        int u = __shfl_up_sync(0xffffffffu, x, o);
        if (lane >= o) x += u;
    }
    return x;
}

__global__ void k_scan_all(int N) {
    __shared__ int wsum[32];
    __shared__ int spre;
    int t = threadIdx.x, lane = t & 31, w = t >> 5;
    bool isDeg = blockIdx.x < NB_N;
    int lo  = isDeg ? 0 : NB_N;
    int n   = isDeg ? N : N_GRAPHS;
    int idx = (blockIdx.x - lo) * SCAN_B + t;
    int v   = 0;
    if (idx < n) v = isDeg ? g_degi[idx] : g_gcnt[idx];

    int incl = warp_incl_scan(v, lane);
    if (lane == 31) wsum[w] = incl;
    __syncthreads();
    if (w == 0) wsum[lane] = warp_incl_scan(wsum[lane], lane);
    __syncthreads();
    int blockIncl = incl + (w > 0 ? wsum[w - 1] : 0);
    int blockTot = wsum[31];

    if (t == 0) {
        g_bsum[blockIdx.x] = blockTot;
        __threadfence();
        atomicAdd(&g_arrive, 1);
        while (atomicAdd(&g_arrive, 0) < (int)gridDim.x) { }
    }
    __syncthreads();

    if (w == 0) {
        int pre = 0;
        for (int j = lo + lane; j < (int)blockIdx.x; j += 32) pre += g_bsum[j];
        #pragma unroll
        for (int o = 16; o > 0; o >>= 1) pre += __shfl_down_sync(0xffffffffu, pre, o);
        if (lane == 0) spre = pre;
    }
    __syncthreads();
    int fin = blockIncl + spre;

    if (idx < n) {
        if (isDeg) {
            g_incl[idx]   = fin;
            g_cursor[idx] = fin - v;
            g_dinv[idx]   = rsqrtf((float)(v + 1));   // +1 self loop
        } else {
            g_gincl[idx] = fin;
        }
    }
}

// ---------------- fused: CSR fill (per-edge) + layer-1 fp16 messages ---------
__global__ void k_fill_l1(const int* __restrict__ row,
                          const int* __restrict__ col,
                          const int* __restrict__ x, int E, int N) {
    int i = blockIdx.x * blockDim.x + threadIdx.x;
    if (i < E) {
        int slot = atomicAdd(&g_cursor[col[i]], 1);
        g_csr[slot] = row[i];
    } else {
        int gid = i - E;            // 16 lanes per node
        int node = gid >> 4;
        if (node >= N) return;
        int lane = gid & 15;
        float d = g_dinv[node];
        float4 v = reinterpret_cast<const float4*>(g_tv + (size_t)x[node] * HID)[lane];
        __half2 h0 = __floats2half2_rn(v.x * d, v.y * d);
        __half2 h1 = __floats2half2_rn(v.z * d, v.w * d);
        uint2 u;
        u.x = *reinterpret_cast<unsigned int*>(&h0);
        u.y = *reinterpret_cast<unsigned int*>(&h1);
        reinterpret_cast<uint2*>(g_ts)[(size_t)node * 16 + lane] = u;
    }
}

// ---------------- warp CSR gather: ts[c] + sum_{r in N(c)} ts[r] -------------
__device__ __forceinline__ float2 csr_gather(const __half2* __restrict__ ts,
                                             int c, int lane) {
    int start = (c == 0) ? 0 : g_incl[c - 1];
    int end = g_incl[c];
    float2 a0 = __half22float2(ts[(size_t)c * 32 + lane]);
    float2 a1 = make_float2(0.f, 0.f);
    float2 a2 = make_float2(0.f, 0.f);
    float2 a3 = make_float2(0.f, 0.f);
    int e = start;
    for (; e + 4 <= end; e += 4) {
        int r0 = g_csr[e], r1 = g_csr[e + 1], r2 = g_csr[e + 2], r3 = g_csr[e + 3];
        float2 v0 = __half22float2(ts[(size_t)r0 * 32 + lane]);
        float2 v1 = __half22float2(ts[(size_t)r1 * 32 + lane]);
        float2 v2 = __half22float2(ts[(size_t)r2 * 32 + lane]);
        float2 v3 = __half22float2(ts[(size_t)r3 * 32 + lane]);
        a0.x += v0.x; a0.y += v0.y;
        a1.x += v1.x; a1.y += v1.y;
        a2.x += v2.x; a2.y += v2.y;
        a3.x += v3.x; a3.y += v3.y;
    }
    for (; e < end; e++) {
        int r = g_csr[e];
        float2 v = __half22float2(ts[(size_t)r * 32 + lane]);
        a0.x += v.x; a0.y += v.y;
    }
    a0.x += a1.x + a2.x + a3.x;
    a0.y += a1.y + a2.y + a3.y;
    return a0;
}

// ---------------- fused: layer-1 gather + ReLU + GEMM(W2) -> ts2 (fp16) ------
// persistent grid so W2 smem load is amortized
__global__ void k_gather_mm(const float* __restrict__ b1,
                            const float* __restrict__ W2, int n) {
    __shared__ float sW[HID * HID];
    int tid = threadIdx.x;
    for (int i = tid; i < HID * HID; i += blockDim.x) sW[i] = W2[i];
    __syncthreads();
    const float2* sW2 = reinterpret_cast<const float2*>(sW);
    int lane = tid & 31, warp = tid >> 5, wpb = blockDim.x >> 5;
    float2 bb = reinterpret_cast<const float2*>(b1)[lane];
    const __half2* ts = reinterpret_cast<const __half2*>(g_ts);
    for (int c = blockIdx.x * wpb + warp; c < n; c += gridDim.x * wpb) {
        float2 s = csr_gather(ts, c, lane);
        float d = g_dinv[c];
        float ex = fmaxf(fmaf(d, s.x, bb.x), 0.f);   // relu(h) cols 2*lane
        float ey = fmaxf(fmaf(d, s.y, bb.y), 0.f);   // and 2*lane+1
        float a = 0.f, bc = 0.f;
        #pragma unroll
        for (int j = 0; j < 32; j++) {
            float e0 = __shfl_sync(0xffffffffu, ex, j);
            float e1 = __shfl_sync(0xffffffffu, ey, j);
            float2 w0 = sW2[(2 * j) * 32 + lane];
            float2 w1 = sW2[(2 * j + 1) * 32 + lane];
            a  = fmaf(e0, w0.x, a);
            bc = fmaf(e0, w0.y, bc);
            a  = fmaf(e1, w1.x, a);
            bc = fmaf(e1, w1.y, bc);
        }
        reinterpret_cast<__half2*>(g_ts2)[(size_t)c * 32 + lane] =
            __floats2half2_rn(a * d, bc * d);
    }
}

// ---------------- fused: layer-2 gather + ReLU + pool scatter ----------------
__global__ void k_gather_pool(const int* __restrict__ batch,
                              const float* __restrict__ b2, int n) {
    int lane = threadIdx.x & 31;
    int warp = threadIdx.x >> 5;
    int c = blockIdx.x * (blockDim.x >> 5) + warp;
    if (c >= n) return;
    const __half2* ts = reinterpret_cast<const __half2*>(g_ts2);
    float2 s = csr_gather(ts, c, lane);
    float d = g_dinv[c];
    float2 bb = reinterpret_cast<const float2*>(b2)[lane];
    float hx = fmaxf(fmaf(d, s.x, bb.x), 0.f);
    float hy = fmaxf(fmaf(d, s.y, bb.y), 0.f);
    int g = batch[c];
    float* dst = g_sums + (size_t)g * HID + 2 * lane;
    asm volatile("red.global.add.v2.f32 [%0], {%1,%2};"
                 :: "l"(dst), "f"(hx), "f"(hy) : "memory");
}

// ---------------- head: out[g] = (sums[g]/cnt) @ Wl + bl ---------------------
__global__ void k_head(const float* __restrict__ Wl,
                       const float* __restrict__ bl,
                       float* __restrict__ out) {
    int lane = threadIdx.x & 31;
    int warp = threadIdx.x >> 5;
    int g = blockIdx.x * (blockDim.x >> 5) + warp;
    if (g >= N_GRAPHS) return;
    int start = (g == 0) ? 0 : g_gincl[g - 1];
    int cnt = g_gincl[g] - start;
    float inv = 1.0f / fmaxf((float)cnt, 1.0f);
    float s0 = g_sums[(size_t)g * HID + 2 * lane] * inv;
    float s1 = g_sums[(size_t)g * HID + 2 * lane + 1] * inv;
    float a0 = s0 * Wl[(2 * lane) * N_CL + 0] + s1 * Wl[(2 * lane + 1) * N_CL + 0];
    float a1 = s0 * Wl[(2 * lane) * N_CL + 1] + s1 * Wl[(2 * lane + 1) * N_CL + 1];
    #pragma unroll
    for (int off = 16; off > 0; off >>= 1) {
        a0 += __shfl_down_sync(0xffffffffu, a0, off);
        a1 += __shfl_down_sync(0xffffffffu, a1, off);
    }
    if (lane == 0) {
        out[g * N_CL + 0] = a0 + bl[0];
        out[g * N_CL + 1] = a1 + bl[1];
    }
}

// ---------------- launch ----------------------------------------------------
extern "C" void kernel_launch(void* const* d_in, const int* in_sizes, int n_in,
                              void* d_out, int out_size) {
    const int*   x     = (const int*)  d_in[0];
    const int*   eidx  = (const int*)  d_in[1];
    const int*   batch = (const int*)  d_in[2];
    const float* emb   = (const float*)d_in[3];
    const float* W1    = (const float*)d_in[4];
    const float* b1    = (const float*)d_in[5];
    const float* W2    = (const float*)d_in[6];
    const float* b2    = (const float*)d_in[7];
    const float* Wl    = (const float*)d_in[8];
    const float* bl    = (const float*)d_in[9];
    float* out = (float*)d_out;

    const int N = in_sizes[0];
    const int E = in_sizes[1] / 2;
    const int V = in_sizes[3] / HID;
    const int* row = eidx;       // sources
    const int* col = eidx + E;   // targets

    const int T = 256;
    const int ZB = (N_GRAPHS * HID + T - 1) / T;   // covers degi/gcnt/sums

    // zero scratch + vocab GEMM (one launch)
    k_vocab_zero<<<VB + ZB, T>>>(emb, W1, N, V);

    // counts -> dual scan -> CSR fill + layer-1 messages
    k_count   <<<(E + N + T - 1) / T, T>>>(col, batch, E, N);
    k_scan_all<<<NB_N + NB_G, SCAN_B>>>(N);
    k_fill_l1 <<<(E + 16 * N + T - 1) / T, T>>>(row, col, x, E, N);

    // layer 1 gather + GEMM(W2) fused  -> ts2
    k_gather_mm<<<2048, 256>>>(b1, W2, N);

    // layer 2 gather + pool scatter fused
    k_gather_pool<<<(N + 7) / 8, 256>>>(batch, b2, N);

    // head
    k_head<<<(N_GRAPHS + 7) / 8, 256>>>(Wl, bl, out);
}

// round 9
// speedup vs baseline: 2.0772x; 1.0118x over previous
#include <cuda_runtime.h>
#include <cuda_fp16.h>
#include <cuda_bf16.h>
#include <cstdint>

#define N_NODESC 100000
#define N_EDGESC 1600000
#define N_GRAPHS 2048
#define VOCABC   1000
#define HID      64
#define N_CL     2
#define SCAN_B   1024
#define NB_N     ((N_NODESC + SCAN_B - 1) / SCAN_B)   // 98
#define NB_G     ((N_GRAPHS + SCAN_B - 1) / SCAN_B)   // 2
#define VB       ((VOCABC + 7) / 8)                   // vocab blocks (8 rows/block)

// ---------------- scratch (device globals; referenced ONLY from device code) -
__device__ int            g_degi[N_NODESC];
__device__ int            g_incl[N_NODESC];    // inclusive scan of deg (CSR row ends)
__device__ int            g_cursor[N_NODESC];  // exclusive prefix (read-only in fill)
__device__ unsigned short g_rank[N_EDGESC];    // edge rank within its target group
__device__ int            g_gcnt[N_GRAPHS];
__device__ int            g_gincl[N_GRAPHS];
__device__ int            g_bsum[NB_N + NB_G];
__device__ int            g_arrive;
__device__ float          g_dinv[N_NODESC];
__device__ int            g_csr[N_EDGESC];     // source node per CSR slot
__device__ float          g_tv[VOCABC * HID];  // emb @ W1 (fp32 vocab table)
__device__ __half         g_ts [(size_t)N_NODESC * HID];  // layer-1 messages (fp16)
__device__ __half         g_ts2[(size_t)N_NODESC * HID];  // layer-2 messages (fp16)
__device__ float          g_sums[(size_t)N_GRAPHS * HID]; // pooled sums

// ---------------- fused: zero scratch + vocab GEMM (emb @ W1) ----------------
__global__ void k_vocab_zero(const float* __restrict__ emb,
                             const float* __restrict__ W, int N, int V) {
    __shared__ float sW[HID * HID];
    if (blockIdx.x < VB) {
        int tid = threadIdx.x;
        for (int i = tid; i < HID * HID; i += blockDim.x) sW[i] = W[i];
        __syncthreads();
        int lane = tid & 31, warp = tid >> 5;
        int r = blockIdx.x * 8 + warp;
        if (r >= V) return;
        const float* e = emb + (size_t)r * HID;
        float e_lo = e[lane], e_hi = e[lane + 32];
        float a0 = 0.f, a1 = 0.f;
        #pragma unroll
        for (int k = 0; k < 32; k++) {
            float ek = __shfl_sync(0xffffffffu, e_lo, k);
            a0 = fmaf(ek, sW[k * HID + lane],      a0);
            a1 = fmaf(ek, sW[k * HID + 32 + lane], a1);
        }
        #pragma unroll
        for (int k = 0; k < 32; k++) {
            float ek = __shfl_sync(0xffffffffu, e_hi, k);
            a0 = fmaf(ek, sW[(k + 32) * HID + lane],      a0);
            a1 = fmaf(ek, sW[(k + 32) * HID + 32 + lane], a1);
        }
        g_tv[(size_t)r * HID + lane]      = a0;
        g_tv[(size_t)r * HID + 32 + lane] = a1;
    } else {
        int i = (blockIdx.x - VB) * blockDim.x + threadIdx.x;
        if (i < N) g_degi[i] = 0;
        if (i < N_GRAPHS) g_gcnt[i] = 0;
        if (i < N_GRAPHS * HID) g_sums[i] = 0.f;
        if (i == 0) g_arrive = 0;
    }
}

// ---------------- counts (atomicAdd return value = edge rank) ----------------
__global__ void k_count(const int* __restrict__ col,
                        const int* __restrict__ batch, int E, int N) {
    int i = blockIdx.x * blockDim.x + threadIdx.x;
    if (i < E) {
        int r = atomicAdd(&g_degi[col[i]], 1);
        g_rank[i] = (unsigned short)r;
    } else if (i < E + N) {
        atomicAdd(&g_gcnt[batch[i - E]], 1);
    }
}

// ---------------- one-launch dual scan (all blocks wave-1 resident) ----------
__device__ __forceinline__ int warp_incl_scan(int x, int lane) {
    #pragma unroll
    for (int o = 1; o < 32; o <<= 1) {
        int u = __shfl_up_sync(0xffffffffu, x, o);
        if (lane >= o) x += u;
    }
    return x;
}

__global__ void k_scan_all(int N) {
    __shared__ int wsum[32];
    __shared__ int spre;
    int t = threadIdx.x, lane = t & 31, w = t >> 5;
    bool isDeg = blockIdx.x < NB_N;
    int lo  = isDeg ? 0 : NB_N;
    int n   = isDeg ? N : N_GRAPHS;
    int idx = (blockIdx.x - lo) * SCAN_B + t;
    int v   = 0;
    if (idx < n) v = isDeg ? g_degi[idx] : g_gcnt[idx];

    int incl = warp_incl_scan(v, lane);
    if (lane == 31) wsum[w] = incl;
    __syncthreads();
    if (w == 0) wsum[lane] = warp_incl_scan(wsum[lane], lane);
    __syncthreads();
    int blockIncl = incl + (w > 0 ? wsum[w - 1] : 0);
    int blockTot = wsum[31];

    if (t == 0) {
        g_bsum[blockIdx.x] = blockTot;
        __threadfence();
        atomicAdd(&g_arrive, 1);
        while (atomicAdd(&g_arrive, 0) < (int)gridDim.x) { }
    }
    __syncthreads();

    if (w == 0) {
        int pre = 0;
        for (int j = lo + lane; j < (int)blockIdx.x; j += 32) pre += g_bsum[j];
        #pragma unroll
        for (int o = 16; o > 0; o >>= 1) pre += __shfl_down_sync(0xffffffffu, pre, o);
        if (lane == 0) spre = pre;
    }
    __syncthreads();
    int fin = blockIncl + spre;

    if (idx < n) {
        if (isDeg) {
            g_incl[idx]   = fin;
            g_cursor[idx] = fin - v;                 // exclusive prefix
            g_dinv[idx]   = rsqrtf((float)(v + 1));  // +1 self loop
        } else {
            g_gincl[idx] = fin;
        }
    }
}

// ---------------- fused: CSR fill (rank-based, no atomics) + l1 messages -----
__global__ void k_fill_l1(const int* __restrict__ row,
                          const int* __restrict__ col,
                          const int* __restrict__ x, int E, int N) {
    int i = blockIdx.x * blockDim.x + threadIdx.x;
    if (i < E) {
        int c = col[i];
        int slot = g_cursor[c] + (int)g_rank[i];
        g_csr[slot] = row[i];
    } else {
        int gid = i - E;            // 16 lanes per node
        int node = gid >> 4;
        if (node >= N) return;
        int lane = gid & 15;
        float d = g_dinv[node];
        float4 v = reinterpret_cast<const float4*>(g_tv + (size_t)x[node] * HID)[lane];
        __half2 h0 = __floats2half2_rn(v.x * d, v.y * d);
        __half2 h1 = __floats2half2_rn(v.z * d, v.w * d);
        uint2 u;
        u.x = *reinterpret_cast<unsigned int*>(&h0);
        u.y = *reinterpret_cast<unsigned int*>(&h1);
        reinterpret_cast<uint2*>(g_ts)[(size_t)node * 16 + lane] = u;
    }
}

// ---------------- warp CSR gather: ts[c] + sum_{r in N(c)} ts[r] -------------
__device__ __forceinline__ float2 csr_gather(const __half2* __restrict__ ts,
                                             int c, int lane) {
    int start = (c == 0) ? 0 : g_incl[c - 1];
    int end = g_incl[c];
    float2 a0 = __half22float2(ts[(size_t)c * 32 + lane]);
    float2 a1 = make_float2(0.f, 0.f);
    float2 a2 = make_float2(0.f, 0.f);
    float2 a3 = make_float2(0.f, 0.f);
    int e = start;
    for (; e + 4 <= end; e += 4) {
        int r0 = g_csr[e], r1 = g_csr[e + 1], r2 = g_csr[e + 2], r3 = g_csr[e + 3];
        float2 v0 = __half22float2(ts[(size_t)r0 * 32 + lane]);
        float2 v1 = __half22float2(ts[(size_t)r1 * 32 + lane]);
        float2 v2 = __half22float2(ts[(size_t)r2 * 32 + lane]);
        float2 v3 = __half22float2(ts[(size_t)r3 * 32 + lane]);
        a0.x += v0.x; a0.y += v0.y;
        a1.x += v1.x; a1.y += v1.y;
        a2.x += v2.x; a2.y += v2.y;
        a3.x += v3.x; a3.y += v3.y;
    }
    for (; e < end; e++) {
        int r = g_csr[e];
        float2 v = __half22float2(ts[(size_t)r * 32 + lane]);
        a0.x += v.x; a0.y += v.y;
    }
    a0.x += a1.x + a2.x + a3.x;
    a0.y += a1.y + a2.y + a3.y;
    return a0;
}

// ---------------- fused: layer-1 gather + ReLU + GEMM(W2) -> ts2 (fp16) ------
// GEMM inner loop uses packed fma.rn.f32x2 (2 FMA lanes/instr, fp32 precision)
__global__ void k_gather_mm(const float* __restrict__ b1,
                            const float* __restrict__ W2, int n) {
    __shared__ float  sW[HID * HID];
    __shared__ float4 se[8][32];      // per-warp duplicated-e buffer
    int tid = threadIdx.x;
    for (int i = tid; i < HID * HID; i += blockDim.x) sW[i] = W2[i];
    __syncthreads();
    int lane = tid & 31, warp = tid >> 5, wpb = blockDim.x >> 5;
    float2 bb = reinterpret_cast<const float2*>(b1)[lane];
    const __half2* ts = reinterpret_cast<const __half2*>(g_ts);
    const unsigned long long* wu = reinterpret_cast<const unsigned long long*>(sW);
    const ulonglong2* eu = reinterpret_cast<const ulonglong2*>(&se[warp][0]);
    for (int c = blockIdx.x * wpb + warp; c < n; c += gridDim.x * wpb) {
        float2 s = csr_gather(ts, c, lane);
        float d = g_dinv[c];
        float ex = fmaxf(fmaf(d, s.x, bb.x), 0.f);   // relu(h), col 2*lane
        float ey = fmaxf(fmaf(d, s.y, bb.y), 0.f);   // col 2*lane+1
        __syncwarp();
        se[warp][lane] = make_float4(ex, ex, ey, ey);
        __syncwarp();
        unsigned long long acc = 0ull;               // packed (0.f, 0.f)
        #pragma unroll
        for (int k = 0; k < HID; k += 2) {
            ulonglong2 ee = eu[k >> 1];              // dup(e_k), dup(e_{k+1})
            unsigned long long w0 = wu[k * 32 + lane];
            unsigned long long w1 = wu[(k + 1) * 32 + lane];
            asm("fma.rn.f32x2 %0, %1, %2, %0;" : "+l"(acc) : "l"(ee.x), "l"(w0));
            asm("fma.rn.f32x2 %0, %1, %2, %0;" : "+l"(acc) : "l"(ee.y), "l"(w1));
        }
        float a, bc;
        asm("mov.b64 {%0, %1}, %2;" : "=f"(a), "=f"(bc) : "l"(acc));
        reinterpret_cast<__half2*>(g_ts2)[(size_t)c * 32 + lane] =
            __floats2half2_rn(a * d, bc * d);
    }
}

// ---------------- fused: layer-2 gather + ReLU + pool scatter ----------------
__global__ void k_gather_pool(const int* __restrict__ batch,
                              const float* __restrict__ b2, int n) {
    int lane = threadIdx.x & 31;
    int warp = threadIdx.x >> 5;
    int c = blockIdx.x * (blockDim.x >> 5) + warp;
    if (c >= n) return;
    const __half2* ts = reinterpret_cast<const __half2*>(g_ts2);
    float2 s = csr_gather(ts, c, lane);
    float d = g_dinv[c];
    float2 bb = reinterpret_cast<const float2*>(b2)[lane];
    float hx = fmaxf(fmaf(d, s.x, bb.x), 0.f);
    float hy = fmaxf(fmaf(d, s.y, bb.y), 0.f);
    int g = batch[c];
    float* dst = g_sums + (size_t)g * HID + 2 * lane;
    asm volatile("red.global.add.v2.f32 [%0], {%1,%2};"
                 :: "l"(dst), "f"(hx), "f"(hy) : "memory");
}

// ---------------- head: out[g] = (sums[g]/cnt) @ Wl + bl ---------------------
__global__ void k_head(const float* __restrict__ Wl,
                       const float* __restrict__ bl,
                       float* __restrict__ out) {
    int lane = threadIdx.x & 31;
    int warp = threadIdx.x >> 5;
    int g = blockIdx.x * (blockDim.x >> 5) + warp;
    if (g >= N_GRAPHS) return;
    int start = (g == 0) ? 0 : g_gincl[g - 1];
    int cnt = g_gincl[g] - start;
    float inv = 1.0f / fmaxf((float)cnt, 1.0f);
    float s0 = g_sums[(size_t)g * HID + 2 * lane] * inv;
    float s1 = g_sums[(size_t)g * HID + 2 * lane + 1] * inv;
    float a0 = s0 * Wl[(2 * lane) * N_CL + 0] + s1 * Wl[(2 * lane + 1) * N_CL + 0];
    float a1 = s0 * Wl[(2 * lane) * N_CL + 1] + s1 * Wl[(2 * lane + 1) * N_CL + 1];
    #pragma unroll
    for (int off = 16; off > 0; off >>= 1) {
        a0 += __shfl_down_sync(0xffffffffu, a0, off);
        a1 += __shfl_down_sync(0xffffffffu, a1, off);
    }
    if (lane == 0) {
        out[g * N_CL + 0] = a0 + bl[0];
        out[g * N_CL + 1] = a1 + bl[1];
    }
}

// ---------------- launch ----------------------------------------------------
extern "C" void kernel_launch(void* const* d_in, const int* in_sizes, int n_in,
                              void* d_out, int out_size) {
    const int*   x     = (const int*)  d_in[0];
    const int*   eidx  = (const int*)  d_in[1];
    const int*   batch = (const int*)  d_in[2];
    const float* emb   = (const float*)d_in[3];
    const float* W1    = (const float*)d_in[4];
    const float* b1    = (const float*)d_in[5];
    const float* W2    = (const float*)d_in[6];
    const float* b2    = (const float*)d_in[7];
    const float* Wl    = (const float*)d_in[8];
    const float* bl    = (const float*)d_in[9];
    float* out = (float*)d_out;

    const int N = in_sizes[0];
    const int E = in_sizes[1] / 2;
    const int V = in_sizes[3] / HID;
    const int* row = eidx;       // sources
    const int* col = eidx + E;   // targets

    const int T = 256;
    const int ZB = (N_GRAPHS * HID + T - 1) / T;   // covers degi/gcnt/sums

    // zero scratch + vocab GEMM (one launch)
    k_vocab_zero<<<VB + ZB, T>>>(emb, W1, N, V);

    // counts (+edge ranks) -> dual scan -> CSR fill + layer-1 messages
    k_count   <<<(E + N + T - 1) / T, T>>>(col, batch, E, N);
    k_scan_all<<<NB_N + NB_G, SCAN_B>>>(N);
    k_fill_l1 <<<(E + 16 * N + T - 1) / T, T>>>(row, col, x, E, N);

    // layer 1 gather + GEMM(W2) fused  -> ts2  (single persistent wave)
    k_gather_mm<<<1184, 256>>>(b1, W2, N);

    // layer 2 gather + pool scatter fused
    k_gather_pool<<<(N + 7) / 8, 256>>>(batch, b2, N);

    // head
    k_head<<<(N_GRAPHS + 7) / 8, 256>>>(Wl, bl, out);
}

// round 11
// speedup vs baseline: 2.0862x; 1.0043x over previous
#include <cuda_runtime.h>
#include <cuda_fp16.h>
#include <cuda_bf16.h>
#include <cstdint>

#define N_NODESC 100000
#define N_EDGESC 1600000
#define N_GRAPHS 2048
#define VOCABC   1000
#define HID      64
#define N_CL     2
#define SCAN_B   1024
#define NB_N     ((N_NODESC + SCAN_B - 1) / SCAN_B)   // 98
#define NB_G     ((N_GRAPHS + SCAN_B - 1) / SCAN_B)   // 2
#define VB       ((VOCABC + 7) / 8)                   // vocab blocks (8 rows/block)

// ---------------- scratch (device globals; referenced ONLY from device code) -
__device__ int            g_degi[N_NODESC];
__device__ int            g_incl[N_NODESC];    // inclusive scan of deg (CSR row ends)
__device__ int            g_cursor[N_NODESC];  // exclusive prefix (read-only in fill)
__device__ unsigned short g_rank[N_EDGESC];    // edge rank within its target group
__device__ int            g_gcnt[N_GRAPHS];
__device__ int            g_gincl[N_GRAPHS];
__device__ int            g_bsum[NB_N + NB_G];
__device__ int            g_arrive;
__device__ float          g_dinv[N_NODESC];
__device__ int            g_csr[N_EDGESC];     // source node per CSR slot
__device__ float          g_tv[VOCABC * HID];  // emb @ W1 (fp32 vocab table)
__device__ __half         g_ts [(size_t)N_NODESC * HID];  // layer-1 messages (fp16)
__device__ __half         g_ts2[(size_t)N_NODESC * HID];  // layer-2 messages (fp16)
__device__ float          g_sums[(size_t)N_GRAPHS * HID]; // pooled sums

// ---------------- zero scratch ----------------------------------------------
__global__ void k_zero(int N) {
    int i = blockIdx.x * blockDim.x + threadIdx.x;
    if (i < N) g_degi[i] = 0;
    if (i < N_GRAPHS) g_gcnt[i] = 0;
    if (i < N_GRAPHS * HID) g_sums[i] = 0.f;
    if (i == 0) g_arrive = 0;
}

// ---------------- fused: counts (+edge ranks) + vocab GEMM -------------------
// first VB blocks: g_tv = emb @ W1 ; remaining blocks: degree/graph counting.
// The GEMM's FMA work overlaps the count blocks' atomic latency.
__global__ void k_count_vocab(const int* __restrict__ col,
                              const int* __restrict__ batch,
                              const float* __restrict__ emb,
                              const float* __restrict__ W, int E, int N, int V) {
    __shared__ float sW[HID * HID];
    if (blockIdx.x < VB) {
        int tid = threadIdx.x;
        for (int i = tid; i < HID * HID; i += blockDim.x) sW[i] = W[i];
        __syncthreads();
        int lane = tid & 31, warp = tid >> 5;
        int r = blockIdx.x * 8 + warp;
        if (r >= V) return;
        const float* e = emb + (size_t)r * HID;
        float e_lo = e[lane], e_hi = e[lane + 32];
        float a0 = 0.f, a1 = 0.f;
        #pragma unroll
        for (int k = 0; k < 32; k++) {
            float ek = __shfl_sync(0xffffffffu, e_lo, k);
            a0 = fmaf(ek, sW[k * HID + lane],      a0);
            a1 = fmaf(ek, sW[k * HID + 32 + lane], a1);
        }
        #pragma unroll
        for (int k = 0; k < 32; k++) {
            float ek = __shfl_sync(0xffffffffu, e_hi, k);
            a0 = fmaf(ek, sW[(k + 32) * HID + lane],      a0);
            a1 = fmaf(ek, sW[(k + 32) * HID + 32 + lane], a1);
        }
        g_tv[(size_t)r * HID + lane]      = a0;
        g_tv[(size_t)r * HID + 32 + lane] = a1;
    } else {
        int i = (blockIdx.x - VB) * blockDim.x + threadIdx.x;
        if (i < E) {
            int r = atomicAdd(&g_degi[col[i]], 1);
            g_rank[i] = (unsigned short)r;
        } else if (i < E + N) {
            atomicAdd(&g_gcnt[batch[i - E]], 1);
        }
    }
}

// ---------------- one-launch dual scan (all blocks wave-1 resident) ----------
__device__ __forceinline__ int warp_incl_scan(int x, int lane) {
    #pragma unroll
    for (int o = 1; o < 32; o <<= 1) {
        int u = __shfl_up_sync(0xffffffffu, x, o);
        if (lane >= o) x += u;
    }
    return x;
}

__global__ void k_scan_all(int N) {
    __shared__ int wsum[32];
    __shared__ int spre;
    int t = threadIdx.x, lane = t & 31, w = t >> 5;
    bool isDeg = blockIdx.x < NB_N;
    int lo  = isDeg ? 0 : NB_N;
    int n   = isDeg ? N : N_GRAPHS;
    int idx = (blockIdx.x - lo) * SCAN_B + t;
    int v   = 0;
    if (idx < n) v = isDeg ? g_degi[idx] : g_gcnt[idx];

    int incl = warp_incl_scan(v, lane);
    if (lane == 31) wsum[w] = incl;
    __syncthreads();
    if (w == 0) wsum[lane] = warp_incl_scan(wsum[lane], lane);
    __syncthreads();
    int blockIncl = incl + (w > 0 ? wsum[w - 1] : 0);
    int blockTot = wsum[31];

    if (t == 0) {
        g_bsum[blockIdx.x] = blockTot;
        __threadfence();
        atomicAdd(&g_arrive, 1);
        while (atomicAdd(&g_arrive, 0) < (int)gridDim.x) { }
    }
    __syncthreads();

    if (w == 0) {
        int pre = 0;
        for (int j = lo + lane; j < (int)blockIdx.x; j += 32) pre += g_bsum[j];
        #pragma unroll
        for (int o = 16; o > 0; o >>= 1) pre += __shfl_down_sync(0xffffffffu, pre, o);
        if (lane == 0) spre = pre;
    }
    __syncthreads();
    int fin = blockIncl + spre;

    if (idx < n) {
        if (isDeg) {
            g_incl[idx]   = fin;
            g_cursor[idx] = fin - v;                 // exclusive prefix
            g_dinv[idx]   = rsqrtf((float)(v + 1));  // +1 self loop
        } else {
            g_gincl[idx] = fin;
        }
    }
}

// ---------------- fused: CSR fill (rank-based, no atomics) + l1 messages -----
__global__ void k_fill_l1(const int* __restrict__ row,
                          const int* __restrict__ col,
                          const int* __restrict__ x, int E, int N) {
    int i = blockIdx.x * blockDim.x + threadIdx.x;
    if (i < E) {
        int c = col[i];
        int slot = g_cursor[c] + (int)g_rank[i];
        g_csr[slot] = row[i];
    } else {
        int gid = i - E;            // 16 lanes per node
        int node = gid >> 4;
        if (node >= N) return;
        int lane = gid & 15;
        float d = g_dinv[node];
        float4 v = reinterpret_cast<const float4*>(g_tv + (size_t)x[node] * HID)[lane];
        __half2 h0 = __floats2half2_rn(v.x * d, v.y * d);
        __half2 h1 = __floats2half2_rn(v.z * d, v.w * d);
        uint2 u;
        u.x = *reinterpret_cast<unsigned int*>(&h0);
        u.y = *reinterpret_cast<unsigned int*>(&h1);
        reinterpret_cast<uint2*>(g_ts)[(size_t)node * 16 + lane] = u;
    }
}

// ---------------- warp CSR gather, MLP=8 (index-prefetch batching) -----------
__device__ __forceinline__ float2 csr_gather(const __half2* __restrict__ ts,
                                             int c, int lane) {
    int start = (c == 0) ? 0 : g_incl[c - 1];
    int end = g_incl[c];
    float2 a0 = __half22float2(ts[(size_t)c * 32 + lane]);
    float2 a1 = make_float2(0.f, 0.f);
    int e = start;
    while (e + 8 <= end) {
        int r[8];
        #pragma unroll
        for (int j = 0; j < 8; j++) r[j] = g_csr[e + j];
        float2 v[8];
        #pragma unroll
        for (int j = 0; j < 8; j++) v[j] = __half22float2(ts[(size_t)r[j] * 32 + lane]);
        #pragma unroll
        for (int j = 0; j < 8; j += 2) {
            a0.x += v[j].x;     a0.y += v[j].y;
            a1.x += v[j + 1].x; a1.y += v[j + 1].y;
        }
        e += 8;
    }
    if (e + 4 <= end) {
        int r[4];
        #pragma unroll
        for (int j = 0; j < 4; j++) r[j] = g_csr[e + j];
        float2 v[4];
        #pragma unroll
        for (int j = 0; j < 4; j++) v[j] = __half22float2(ts[(size_t)r[j] * 32 + lane]);
        a0.x += v[0].x + v[2].x; a0.y += v[0].y + v[2].y;
        a1.x += v[1].x + v[3].x; a1.y += v[1].y + v[3].y;
        e += 4;
    }
    for (; e < end; e++) {
        int r = g_csr[e];
        float2 v = __half22float2(ts[(size_t)r * 32 + lane]);
        a0.x += v.x; a0.y += v.y;
    }
    a0.x += a1.x;
    a0.y += a1.y;
    return a0;
}

// ---------------- fused: layer-1 gather + ReLU + GEMM(W2) -> ts2 (fp16) ------
__global__ void k_gather_mm(const float* __restrict__ b1,
                            const float* __restrict__ W2, int n) {
    __shared__ float  sW[HID * HID];
    __shared__ float4 se[8][32];      // per-warp duplicated-e buffer
    int tid = threadIdx.x;
    for (int i = tid; i < HID * HID; i += blockDim.x) sW[i] = W2[i];
    __syncthreads();
    int lane = tid & 31, warp = tid >> 5, wpb = blockDim.x >> 5;
    float2 bb = reinterpret_cast<const float2*>(b1)[lane];
    const __half2* ts = reinterpret_cast<const __half2*>(g_ts);
    const unsigned long long* wu = reinterpret_cast<const unsigned long long*>(sW);
    const ulonglong2* eu = reinterpret_cast<const ulonglong2*>(&se[warp][0]);
    for (int c = blockIdx.x * wpb + warp; c < n; c += gridDim.x * wpb) {
        float2 s = csr_gather(ts, c, lane);
        float d = g_dinv[c];
        float ex = fmaxf(fmaf(d, s.x, bb.x), 0.f);   // relu(h), col 2*lane
        float ey = fmaxf(fmaf(d, s.y, bb.y), 0.f);   // col 2*lane+1
        __syncwarp();
        se[warp][lane] = make_float4(ex, ex, ey, ey);
        __syncwarp();
        unsigned long long acc = 0ull;               // packed (0.f, 0.f)
        #pragma unroll
        for (int k = 0; k < HID; k += 2) {
            ulonglong2 ee = eu[k >> 1];              // dup(e_k), dup(e_{k+1})
            unsigned long long w0 = wu[k * 32 + lane];
            unsigned long long w1 = wu[(k + 1) * 32 + lane];
            asm("fma.rn.f32x2 %0, %1, %2, %0;" : "+l"(acc) : "l"(ee.x), "l"(w0));
            asm("fma.rn.f32x2 %0, %1, %2, %0;" : "+l"(acc) : "l"(ee.y), "l"(w1));
        }
        float a, bc;
        asm("mov.b64 {%0, %1}, %2;" : "=f"(a), "=f"(bc) : "l"(acc));
        reinterpret_cast<__half2*>(g_ts2)[(size_t)c * 32 + lane] =
            __floats2half2_rn(a * d, bc * d);
    }
}

// ---------------- fused: layer-2 gather + ReLU + pool scatter (persistent) ---
__global__ void k_gather_pool(const int* __restrict__ batch,
                              const float* __restrict__ b2, int n) {
    int lane = threadIdx.x & 31;
    int warp = threadIdx.x >> 5;
    int wpb = blockDim.x >> 5;
    const __half2* ts = reinterpret_cast<const __half2*>(g_ts2);
    for (int c = blockIdx.x * wpb + warp; c < n; c += gridDim.x * wpb) {
        float2 s = csr_gather(ts, c, lane);
        float d = g_dinv[c];
        float2 bb = reinterpret_cast<const float2*>(b2)[lane];
        float hx = fmaxf(fmaf(d, s.x, bb.x), 0.f);
        float hy = fmaxf(fmaf(d, s.y, bb.y), 0.f);
        int g = batch[c];
        float* dst = g_sums + (size_t)g * HID + 2 * lane;
        asm volatile("red.global.add.v2.f32 [%0], {%1,%2};"
                     :: "l"(dst), "f"(hx), "f"(hy) : "memory");
    }
}

// ---------------- head: out[g] = (sums[g]/cnt) @ Wl + bl ---------------------
__global__ void k_head(const float* __restrict__ Wl,
                       const float* __restrict__ bl,
                       float* __restrict__ out) {
    int lane = threadIdx.x & 31;
    int warp = threadIdx.x >> 5;
    int g = blockIdx.x * (blockDim.x >> 5) + warp;
    if (g >= N_GRAPHS) return;
    int start = (g == 0) ? 0 : g_gincl[g - 1];
    int cnt = g_gincl[g] - start;
    float inv = 1.0f / fmaxf((float)cnt, 1.0f);
    float s0 = g_sums[(size_t)g * HID + 2 * lane] * inv;
    float s1 = g_sums[(size_t)g * HID + 2 * lane + 1] * inv;
    float a0 = s0 * Wl[(2 * lane) * N_CL + 0] + s1 * Wl[(2 * lane + 1) * N_CL + 0];
    float a1 = s0 * Wl[(2 * lane) * N_CL + 1] + s1 * Wl[(2 * lane + 1) * N_CL + 1];
    #pragma unroll
    for (int off = 16; off > 0; off >>= 1) {
        a0 += __shfl_down_sync(0xffffffffu, a0, off);
        a1 += __shfl_down_sync(0xffffffffu, a1, off);
    }
    if (lane == 0) {
        out[g * N_CL + 0] = a0 + bl[0];
        out[g * N_CL + 1] = a1 + bl[1];
    }
}

// ---------------- launch ----------------------------------------------------
extern "C" void kernel_launch(void* const* d_in, const int* in_sizes, int n_in,
                              void* d_out, int out_size) {
    const int*   x     = (const int*)  d_in[0];
    const int*   eidx  = (const int*)  d_in[1];
    const int*   batch = (const int*)  d_in[2];
    const float* emb   = (const float*)d_in[3];
    const float* W1    = (const float*)d_in[4];
    const float* b1    = (const float*)d_in[5];
    const float* W2    = (const float*)d_in[6];
    const float* b2    = (const float*)d_in[7];
    const float* Wl    = (const float*)d_in[8];
    const float* bl    = (const float*)d_in[9];
    float* out = (float*)d_out;

    const int N = in_sizes[0];
    const int E = in_sizes[1] / 2;
    const int V = in_sizes[3] / HID;
    const int* row = eidx;       // sources
    const int* col = eidx + E;   // targets

    const int T = 256;
    const int ZB = (N_GRAPHS * HID + T - 1) / T;   // covers degi/gcnt/sums
    const int CB = (E + N + T - 1) / T;            // count work

    // zero -> fused count+vocab GEMM -> dual scan -> CSR fill + l1 messages
    k_zero       <<<ZB, T>>>(N);
    k_count_vocab<<<VB + CB, T>>>(col, batch, emb, W1, E, N, V);
    k_scan_all   <<<NB_N + NB_G, SCAN_B>>>(N);
    k_fill_l1    <<<(E + 16 * N + T - 1) / T, T>>>(row, col, x, E, N);

    // layer 1 gather + GEMM(W2) fused  -> ts2  (single persistent wave)
    k_gather_mm<<<1184, 256>>>(b1, W2, N);

    // layer 2 gather + pool scatter fused (persistent)
    k_gather_pool<<<1184, 256>>>(batch, b2, N);

    // head
    k_head<<<(N_GRAPHS + 7) / 8, 256>>>(Wl, bl, out);
}